// round 9
// baseline (speedup 1.0000x reference)
#include <cuda_runtime.h>
#include <cuda_bf16.h>
#include <cstdint>

#define BB 8
#define CC 2048
#define FIN 128
#define FF 64
#define NROWS (BB*CC)
#define LOG2E 1.4426950408889634f

// Scratch (__device__ globals: allocation-free rule)
// g_WhP: paired layout, per 64-row group (= global row>>6), 4096 floats:
//   offset = grp64*4096 + kt*128 + col*2 + h,  kt=(q>>3)*4+(q&3), h=(q>>2)&1.
__device__ float g_WhP[(size_t)NROWS * FF];
__device__ float g_s1[NROWS];                 // s1 * log2e
__device__ float g_s2[NROWS];                 // s2 * log2e
__device__ uint32_t g_mask[NROWS][64];        // validity bits: word=(j>>7)*4+(j&3), bit=(j>>2)&31
__device__ float g_ms[NROWS];                 // exact row max of lrelu logits (exp2 domain)
__device__ float g_part[512][64][72];         // per (tile,half): unnorm acc + l at col 64

__device__ __forceinline__ float f2tf32f(float x) {
    uint32_t r;
    asm("cvt.rna.tf32.f32 %0, %1;" : "=r"(r) : "f"(x));
    return __uint_as_float(r);
}
__device__ __forceinline__ float ex2f(float x) {
    float r;
    asm("ex2.approx.f32 %0, %1;" : "=f"(r) : "f"(x));
    return r;
}
__device__ __forceinline__ void mma_tf32(float* c,
                                         uint32_t a0, uint32_t a1, uint32_t a2, uint32_t a3,
                                         uint32_t b0, uint32_t b1) {
    asm volatile(
        "mma.sync.aligned.m16n8k8.row.col.f32.tf32.tf32.f32 "
        "{%0,%1,%2,%3}, {%4,%5,%6,%7}, {%8,%9}, {%0,%1,%2,%3};"
        : "+f"(c[0]), "+f"(c[1]), "+f"(c[2]), "+f"(c[3])
        : "r"(a0), "r"(a1), "r"(a2), "r"(a3), "r"(b0), "r"(b1));
}
__device__ __forceinline__ int hperm(int r) { return r + ((r >> 3) << 2); }

// ---------------------------------------------------------------------------
// Fat kernel: blocks 0..255 = Wh GEMM (+ s1,s2); blocks 256..511 = A->bitmask
// compression (DRAM-bound, overlaps the FMA-bound GEMM blocks on-chip).
// ---------------------------------------------------------------------------
__global__ __launch_bounds__(256) void k_fat(const float* __restrict__ H,
                                             const float* __restrict__ W,
                                             const float* __restrict__ a,
                                             const int* __restrict__ A)
{
    __shared__ float HsT[32][92];
    __shared__ float Ws[32][68];

    int t = threadIdx.x;

    if (blockIdx.x >= 256) {
        // ---- compress: 64 rows/block, one warp per 8 rows ----
        int cb = blockIdx.x - 256;
        int warp = t >> 5, lane = t & 31;
#pragma unroll 1
        for (int rr = 0; rr < 8; rr++) {
            int row = cb * 64 + warp * 8 + rr;
            int diag = row & (CC - 1);
            const int4* src = (const int4*)(A + (size_t)row * CC);
            uint4* dst = (uint4*)(&g_mask[row][0]);
#pragma unroll 4
            for (int it = 0; it < 16; it++) {
                int4 av = __ldcs(&src[it * 32 + lane]);
                int j = it * 128 + lane * 4;
                uint32_t b0 = __ballot_sync(0xffffffffu, (av.x > 0) || (j     == diag));
                uint32_t b1 = __ballot_sync(0xffffffffu, (av.y > 0) || (j + 1 == diag));
                uint32_t b2 = __ballot_sync(0xffffffffu, (av.z > 0) || (j + 2 == diag));
                uint32_t b3 = __ballot_sync(0xffffffffu, (av.w > 0) || (j + 3 == diag));
                if (lane == 0) dst[it] = make_uint4(b0, b1, b2, b3);
            }
        }
        return;
    }

    // ---- Wh GEMM: 64 rows/block ----
    int tx = t & 31, ty = t >> 5;
    int r0 = blockIdx.x * 64;
    float acc[8][2] = {};

    for (int kc = 0; kc < 4; kc++) {
        __syncthreads();
#pragma unroll
        for (int p = 0; p < 2; p++) {
            int idx = t + p * 256;
            int r = idx >> 3, c4 = idx & 7;
            float4 v = *(const float4*)(H + (size_t)(r0 + r) * FIN + kc * 32 + c4 * 4);
            int pr = hperm(r);
            HsT[c4 * 4 + 0][pr] = v.x;
            HsT[c4 * 4 + 1][pr] = v.y;
            HsT[c4 * 4 + 2][pr] = v.z;
            HsT[c4 * 4 + 3][pr] = v.w;
        }
#pragma unroll
        for (int p = 0; p < 2; p++) {
            int idx = t + p * 256;
            int row = idx >> 4, c4 = idx & 15;
            *(float4*)&Ws[row][c4 * 4] = *(const float4*)(W + (size_t)(kc * 32 + row) * FF + c4 * 4);
        }
        __syncthreads();

#pragma unroll
        for (int k = 0; k < 32; k++) {
            float2 w = *(const float2*)&Ws[k][tx * 2];
            float4 h0 = *(const float4*)&HsT[k][ty * 12];
            float4 h1 = *(const float4*)&HsT[k][ty * 12 + 4];
            acc[0][0] = fmaf(h0.x, w.x, acc[0][0]); acc[0][1] = fmaf(h0.x, w.y, acc[0][1]);
            acc[1][0] = fmaf(h0.y, w.x, acc[1][0]); acc[1][1] = fmaf(h0.y, w.y, acc[1][1]);
            acc[2][0] = fmaf(h0.z, w.x, acc[2][0]); acc[2][1] = fmaf(h0.z, w.y, acc[2][1]);
            acc[3][0] = fmaf(h0.w, w.x, acc[3][0]); acc[3][1] = fmaf(h0.w, w.y, acc[3][1]);
            acc[4][0] = fmaf(h1.x, w.x, acc[4][0]); acc[4][1] = fmaf(h1.x, w.y, acc[4][1]);
            acc[5][0] = fmaf(h1.y, w.x, acc[5][0]); acc[5][1] = fmaf(h1.y, w.y, acc[5][1]);
            acc[6][0] = fmaf(h1.z, w.x, acc[6][0]); acc[6][1] = fmaf(h1.z, w.y, acc[6][1]);
            acc[7][0] = fmaf(h1.w, w.x, acc[7][0]); acc[7][1] = fmaf(h1.w, w.y, acc[7][1]);
        }
    }

    float a10 = a[tx * 2], a11 = a[tx * 2 + 1];
    float a20 = a[FF + tx * 2], a21 = a[FF + tx * 2 + 1];
#pragma unroll
    for (int rr = 0; rr < 8; rr++) {
        int r = r0 + ty * 8 + rr;
        float p1 = acc[rr][0] * a10 + acc[rr][1] * a11;
        float p2 = acc[rr][0] * a20 + acc[rr][1] * a21;
#pragma unroll
        for (int off = 16; off; off >>= 1) {
            p1 += __shfl_xor_sync(0xffffffffu, p1, off);
            p2 += __shfl_xor_sync(0xffffffffu, p2, off);
        }
        if (tx == 0) { g_s1[r] = p1 * LOG2E; g_s2[r] = p2 * LOG2E; }
    }

    float* dst = g_WhP + (size_t)blockIdx.x * 4096;
#pragma unroll
    for (int rr = 0; rr < 4; rr++) {
        int kt = ty * 4 + rr;
        float4 v;
        v.x = f2tf32f(acc[rr][0]);
        v.y = f2tf32f(acc[rr + 4][0]);
        v.z = f2tf32f(acc[rr][1]);
        v.w = f2tf32f(acc[rr + 4][1]);
        *(float4*)(dst + kt * 128 + tx * 4) = v;
    }
}

// ---------------------------------------------------------------------------
// k_rowmax: exact global row max from bitmask + s2.  64 rows/block, grid 256.
// Mask words loaded uniformly (broadcast), bit index = lane, s2 via float4 LDS.
// ---------------------------------------------------------------------------
__global__ __launch_bounds__(256) void k_rowmax()
{
    __shared__ float s2S[CC];
    int t = threadIdx.x;
    int warp = t >> 5, lane = t & 31;
    int b  = blockIdx.x >> 5;
    int i0 = (blockIdx.x & 31) << 6;

    for (int q = t; q < CC; q += 256) s2S[q] = g_s2[b * CC + q];
    __syncthreads();

    const float4* s2v4 = (const float4*)s2S;
#pragma unroll 1
    for (int rr = 0; rr < 8; rr++) {
        int r = b * CC + i0 + warp * 8 + rr;
        const uint4* mrow = (const uint4*)(&g_mask[r][0]);
        float m2 = -3.0e38f;
#pragma unroll 4
        for (int it = 0; it < 16; it++) {
            uint4 mw = mrow[it];                    // uniform: broadcast to all lanes
            float4 sv = s2v4[it * 32 + lane];       // j = it*128 + lane*4 + c
            m2 = fmaxf(m2, ((mw.x >> lane) & 1u) ? sv.x : -3.0e38f);
            m2 = fmaxf(m2, ((mw.y >> lane) & 1u) ? sv.y : -3.0e38f);
            m2 = fmaxf(m2, ((mw.z >> lane) & 1u) ? sv.z : -3.0e38f);
            m2 = fmaxf(m2, ((mw.w >> lane) & 1u) ? sv.w : -3.0e38f);
        }
#pragma unroll
        for (int off = 16; off; off >>= 1)
            m2 = fmaxf(m2, __shfl_xor_sync(0xffffffffu, m2, off));
        if (lane == 0) {
            float x = g_s1[r] + m2;
            g_ms[r] = fmaxf(x, 0.2f * x);           // exact row max (exp2 domain)
        }
    }
}

// ---------------------------------------------------------------------------
// k_out: split-j partial masked-softmax @ Wh, compute-only (no A stream).
// Grid 512, 4 blocks/SM. 64 rows x 1024 j per block. Mask words from L2.
// ---------------------------------------------------------------------------
// dynamic smem (bytes):
//   s2S    : float [1024]         @ 0      (4096)
//   s2pair : float2[512]          @ 4096   (4096)
//   whsP   : float [2][32][68][2] @ 8192   (34816)  (aliased as accS at end)
//   s1s    : float [64]           @ 43008  (256)
//   ms     : float [64]           @ 43264  (256)
#define KOUT_SMEM 43520

__global__ __launch_bounds__(256, 4) void k_out()
{
    extern __shared__ char smemraw[];
    float*  s2S    = (float*)(smemraw);
    float2* s2pair = (float2*)(smemraw + 4096);
    float*  whsP   = (float*)(smemraw + 8192);
    float*  s1s    = (float*)(smemraw + 43008);
    float*  ms     = (float*)(smemraw + 43264);

    int t = threadIdx.x;
    int lane = t & 31;
    int warp = t >> 5;
    int grp  = t >> 7;
    int lt   = t & 127;
    int wg   = warp & 3;
    int g = lane >> 2, tg = lane & 3;
    int m0 = wg * 16;

    int bid  = blockIdx.x;
    int half = bid & 1;
    int tile = bid >> 1;
    int b  = tile >> 5;
    int i0 = (tile & 31) << 6;
    int J0 = half << 10;

    if (t < 64) {
        int r = b * CC + i0 + t;
        s1s[t] = g_s1[r];
        ms[t]  = g_ms[r];
    }
    for (int q = t; q < 1024; q += 256) s2S[q] = g_s2[b * CC + J0 + q];
    __syncthreads();

#pragma unroll
    for (int p = 0; p < 2; p++) {
        int idx = t + p * 256;
        int gj = idx >> 2, tgq = idx & 3;
        s2pair[idx] = make_float2(s2S[gj * 8 + tgq], s2S[gj * 8 + tgq + 4]);
    }

    // folded row constants (global exact row max)
    float cA  = s1s[m0 + g]            - ms[m0 + g];
    float c5A = 0.2f * s1s[m0 + g]     - ms[m0 + g];
    float cB  = s1s[m0 + g + 8]        - ms[m0 + g + 8];
    float c5B = 0.2f * s1s[m0 + g + 8] - ms[m0 + g + 8];

    const uint32_t* mrA = &g_mask[b * CC + i0 + m0 + g][half * 32];
    const uint32_t* mrB = &g_mask[b * CC + i0 + m0 + g + 8][half * 32];

    float4 acc[8];
#pragma unroll
    for (int nf = 0; nf < 8; nf++) acc[nf] = make_float4(0.f, 0.f, 0.f, 0.f);
    float lA = 0.f, lB = 0.f;

    int gbase = (b * 32) + (J0 >> 6);

    for (int o = 0; o < 8; o++) {
        uint32_t mA = __ldg(&mrA[o * 4 + tg]);     // hot L2; latency hides behind staging
        uint32_t mB = __ldg(&mrB[o * 4 + tg]);

        __syncthreads();
        {   // stage 128 Wh rows (paired layout, straight copy)
            const float4* src = (const float4*)(g_WhP + (size_t)(gbase + o * 2) * 4096);
#pragma unroll
            for (int p = 0; p < 8; p++) {
                int idx = t + p * 256;
                int gs = idx >> 10, rest = idx & 1023;
                int kt = rest >> 5, f4i = rest & 31;
                *(float4*)(whsP + gs * 4352 + kt * 136 + f4i * 4) = src[idx];
            }
        }
        __syncthreads();

        const float2* s2pg = s2pair + ((o * 128 + grp * 64) >> 3) * 4 + tg;
        const float*  wpg  = whsP + grp * 4352 + tg * 136;

#pragma unroll
        for (int kk = 0; kk < 8; kk++) {
            float2 sp = s2pg[kk * 4];
            int bit0 = grp * 16 + kk * 2, bit1 = bit0 + 1;

            float ya0 = fmaxf(sp.x + cA, fmaf(0.2f, sp.x, c5A));
            float ya1 = fmaxf(sp.y + cA, fmaf(0.2f, sp.y, c5A));
            float yb0 = fmaxf(sp.x + cB, fmaf(0.2f, sp.x, c5B));
            float yb1 = fmaxf(sp.y + cB, fmaf(0.2f, sp.y, c5B));

            ya0 = ((mA >> bit0) & 1u) ? ya0 : -1000.f;
            ya1 = ((mA >> bit1) & 1u) ? ya1 : -1000.f;
            yb0 = ((mB >> bit0) & 1u) ? yb0 : -1000.f;
            yb1 = ((mB >> bit1) & 1u) ? yb1 : -1000.f;

            float pa0 = f2tf32f(ex2f(ya0));
            float pa1 = f2tf32f(ex2f(ya1));
            float pb0 = f2tf32f(ex2f(yb0));
            float pb1 = f2tf32f(ex2f(yb1));
            lA += pa0 + pa1;
            lB += pb0 + pb1;

            uint32_t a0 = __float_as_uint(pa0);
            uint32_t a1 = __float_as_uint(pb0);
            uint32_t a2 = __float_as_uint(pa1);
            uint32_t a3 = __float_as_uint(pb1);

            const float* wk = wpg + kk * 4 * 136 + g * 2;
#pragma unroll
            for (int nf = 0; nf < 8; nf++) {
                float2 wp = *(const float2*)(wk + nf * 16);
                mma_tf32((float*)&acc[nf],
                         a0, a1, a2, a3,
                         __float_as_uint(wp.x), __float_as_uint(wp.y));
            }
        }
    }

    // ---- cross-group reduction (alias whsP) + scratch write ----
    __syncthreads();
    float4* accS = (float4*)whsP;
    if (grp == 1) {
#pragma unroll
        for (int nf = 0; nf < 8; nf++) accS[lt * 9 + nf] = acc[nf];
        accS[lt * 9 + 8] = make_float4(lA, lB, 0.f, 0.f);
    }
    __syncthreads();
    if (grp == 0) {
#pragma unroll
        for (int nf = 0; nf < 8; nf++) {
            float4 o = accS[lt * 9 + nf];
            acc[nf].x += o.x; acc[nf].y += o.y; acc[nf].z += o.z; acc[nf].w += o.w;
        }
        float4 lo = accS[lt * 9 + 8];
        lA += lo.x; lB += lo.y;
        lA += __shfl_xor_sync(0xffffffffu, lA, 1);
        lA += __shfl_xor_sync(0xffffffffu, lA, 2);
        lB += __shfl_xor_sync(0xffffffffu, lB, 1);
        lB += __shfl_xor_sync(0xffffffffu, lB, 2);

        int row_lo = m0 + g, row_hi = row_lo + 8;
#pragma unroll
        for (int nf = 0; nf < 8; nf++) {
            int col = nf * 8 + 2 * tg;
            *(float2*)&g_part[bid][row_lo][col] = make_float2(acc[nf].x, acc[nf].y);
            *(float2*)&g_part[bid][row_hi][col] = make_float2(acc[nf].z, acc[nf].w);
        }
        if (tg == 0) {
            g_part[bid][row_lo][64] = lA;
            g_part[bid][row_hi][64] = lB;
        }
    }
}

// ---------------------------------------------------------------------------
// k_comb: halves share the same (global) shift -> plain add, divide, relu.
// ---------------------------------------------------------------------------
__global__ __launch_bounds__(256) void k_comb(float* __restrict__ out)
{
    int tile = blockIdx.x;
    int t = threadIdx.x;
    int ri = t >> 2, cq = t & 3;
    int p0 = tile * 2, p1 = p0 + 1;

    float l = g_part[p0][ri][64] + g_part[p1][ri][64];
    float inv = 1.f / l;                       // l >= 1 (exact global max)

    size_t rowbase = ((size_t)tile * 64 + ri) * FF;
#pragma unroll
    for (int q = 0; q < 4; q++) {
        int col = cq * 16 + q * 4;
        float4 a0 = *(const float4*)&g_part[p0][ri][col];
        float4 a1 = *(const float4*)&g_part[p1][ri][col];
        float4 v;
        v.x = fmaxf((a0.x + a1.x) * inv, 0.f);
        v.y = fmaxf((a0.y + a1.y) * inv, 0.f);
        v.z = fmaxf((a0.z + a1.z) * inv, 0.f);
        v.w = fmaxf((a0.w + a1.w) * inv, 0.f);
        *(float4*)(out + rowbase + col) = v;
    }
}

// ---------------------------------------------------------------------------
extern "C" void kernel_launch(void* const* d_in, const int* in_sizes, int n_in,
                              void* d_out, int out_size)
{
    const float* H = (const float*)d_in[0];   // (8, 2048, 128) f32
    const int*   A = (const int*)d_in[1];     // (8, 2048, 2048) i32
    const float* W = (const float*)d_in[2];   // (128, 64) f32
    const float* a = (const float*)d_in[3];   // (128,) f32
    float* out = (float*)d_out;               // (8, 2048, 64) f32

    cudaFuncSetAttribute(k_out, cudaFuncAttributeMaxDynamicSharedMemorySize, KOUT_SMEM);

    k_fat<<<512, 256>>>(H, W, a, A);
    k_rowmax<<<256, 256>>>();
    k_out<<<512, 256, KOUT_SMEM>>>();
    k_comb<<<256, 256>>>(out);
}

// round 11
// speedup vs baseline: 1.4578x; 1.4578x over previous
#include <cuda_runtime.h>
#include <cuda_bf16.h>
#include <cstdint>

#define BB 8
#define CC 2048
#define FIN 128
#define FF 64
#define NROWS (BB*CC)
#define LOG2E 1.4426950408889634f

// Scratch (__device__ globals: allocation-free rule)
// g_WhP: paired layout, per 64-row group (= global row>>6), 4096 floats:
//   offset = grp64*4096 + kt*128 + col*2 + h,  kt=(q>>3)*4+(q&3), h=(q>>2)&1.
__device__ float g_WhP[(size_t)NROWS * FF];
__device__ float g_s1[NROWS];                 // s1 * log2e
__device__ float g_s2[NROWS];                 // s2 * log2e
__device__ float g_part[512][64][72];         // per (tile,half): unnorm acc + l at col 64
__device__ float g_partm[512][64];            // per (tile,half): running row max (exp2 dom)

__device__ __forceinline__ float f2tf32f(float x) {
    uint32_t r;
    asm("cvt.rna.tf32.f32 %0, %1;" : "=r"(r) : "f"(x));
    return __uint_as_float(r);
}
__device__ __forceinline__ float ex2f(float x) {
    float r;
    asm("ex2.approx.f32 %0, %1;" : "=f"(r) : "f"(x));
    return r;
}
__device__ __forceinline__ void mma_tf32(float* c,
                                         uint32_t a0, uint32_t a1, uint32_t a2, uint32_t a3,
                                         uint32_t b0, uint32_t b1) {
    asm volatile(
        "mma.sync.aligned.m16n8k8.row.col.f32.tf32.tf32.f32 "
        "{%0,%1,%2,%3}, {%4,%5,%6,%7}, {%8,%9}, {%0,%1,%2,%3};"
        : "+f"(c[0]), "+f"(c[1]), "+f"(c[2]), "+f"(c[3])
        : "r"(a0), "r"(a1), "r"(a2), "r"(a3), "r"(b0), "r"(b1));
}
__device__ __forceinline__ int hperm(int r) { return r + ((r >> 3) << 2); }

// ---------------------------------------------------------------------------
// Kernel 1 (R8 verbatim): Wh = H @ W (64 rows/block, grid 256), + s1,s2.
// ---------------------------------------------------------------------------
__global__ __launch_bounds__(256) void k_wh(const float* __restrict__ H,
                                            const float* __restrict__ W,
                                            const float* __restrict__ a)
{
    __shared__ float HsT[32][92];
    __shared__ float Ws[32][68];

    int t  = threadIdx.x;
    int tx = t & 31;
    int ty = t >> 5;
    int r0 = blockIdx.x * 64;

    float acc[8][2] = {};

    for (int kc = 0; kc < 4; kc++) {
        __syncthreads();
#pragma unroll
        for (int p = 0; p < 2; p++) {
            int idx = t + p * 256;
            int r = idx >> 3, c4 = idx & 7;
            float4 v = *(const float4*)(H + (size_t)(r0 + r) * FIN + kc * 32 + c4 * 4);
            int pr = hperm(r);
            HsT[c4 * 4 + 0][pr] = v.x;
            HsT[c4 * 4 + 1][pr] = v.y;
            HsT[c4 * 4 + 2][pr] = v.z;
            HsT[c4 * 4 + 3][pr] = v.w;
        }
#pragma unroll
        for (int p = 0; p < 2; p++) {
            int idx = t + p * 256;
            int row = idx >> 4, c4 = idx & 15;
            *(float4*)&Ws[row][c4 * 4] = *(const float4*)(W + (size_t)(kc * 32 + row) * FF + c4 * 4);
        }
        __syncthreads();

#pragma unroll
        for (int k = 0; k < 32; k++) {
            float2 w = *(const float2*)&Ws[k][tx * 2];
            float4 h0 = *(const float4*)&HsT[k][ty * 12];
            float4 h1 = *(const float4*)&HsT[k][ty * 12 + 4];
            acc[0][0] = fmaf(h0.x, w.x, acc[0][0]); acc[0][1] = fmaf(h0.x, w.y, acc[0][1]);
            acc[1][0] = fmaf(h0.y, w.x, acc[1][0]); acc[1][1] = fmaf(h0.y, w.y, acc[1][1]);
            acc[2][0] = fmaf(h0.z, w.x, acc[2][0]); acc[2][1] = fmaf(h0.z, w.y, acc[2][1]);
            acc[3][0] = fmaf(h0.w, w.x, acc[3][0]); acc[3][1] = fmaf(h0.w, w.y, acc[3][1]);
            acc[4][0] = fmaf(h1.x, w.x, acc[4][0]); acc[4][1] = fmaf(h1.x, w.y, acc[4][1]);
            acc[5][0] = fmaf(h1.y, w.x, acc[5][0]); acc[5][1] = fmaf(h1.y, w.y, acc[5][1]);
            acc[6][0] = fmaf(h1.z, w.x, acc[6][0]); acc[6][1] = fmaf(h1.z, w.y, acc[6][1]);
            acc[7][0] = fmaf(h1.w, w.x, acc[7][0]); acc[7][1] = fmaf(h1.w, w.y, acc[7][1]);
        }
    }

    float a10 = a[tx * 2], a11 = a[tx * 2 + 1];
    float a20 = a[FF + tx * 2], a21 = a[FF + tx * 2 + 1];
#pragma unroll
    for (int rr = 0; rr < 8; rr++) {
        int r = r0 + ty * 8 + rr;
        float p1 = acc[rr][0] * a10 + acc[rr][1] * a11;
        float p2 = acc[rr][0] * a20 + acc[rr][1] * a21;
#pragma unroll
        for (int off = 16; off; off >>= 1) {
            p1 += __shfl_xor_sync(0xffffffffu, p1, off);
            p2 += __shfl_xor_sync(0xffffffffu, p2, off);
        }
        if (tx == 0) { g_s1[r] = p1 * LOG2E; g_s2[r] = p2 * LOG2E; }
    }

    float* dst = g_WhP + (size_t)blockIdx.x * 4096;
#pragma unroll
    for (int rr = 0; rr < 4; rr++) {
        int kt = ty * 4 + rr;
        float4 v;
        v.x = f2tf32f(acc[rr][0]);
        v.y = f2tf32f(acc[rr + 4][0]);
        v.z = f2tf32f(acc[rr][1]);
        v.w = f2tf32f(acc[rr + 4][1]);
        *(float4*)(dst + kt * 128 + tx * 4) = v;
    }
}

// ---------------------------------------------------------------------------
// k_out: SINGLE-PASS online-softmax @ Wh. Grid 512, 4 blocks/SM, one wave.
// 64 rows x 1024 j per block. Per 128-j chunk: stage Wh + compress A chunk
// (ballot -> smem mask, chunk max of valid s2), update running row max,
// rescale accumulators, exp+MMA. A DRAM stream overlaps MMA of prior chunks.
// ---------------------------------------------------------------------------
// dynamic smem (bytes):
//   maskC : uint32[64][8]       @ 0      (2048)   per-chunk validity words
//   s2S   : float [1024]        @ 2048   (4096)
//   s2pair: float2[512]         @ 6144   (4096)
//   whsP  : float [2][4352]     @ 10240  (34816)  (aliased as accS at end)
//   s1s   : float [64]          @ 45056  (256)
//   msS   : float [64]          @ 45312  (256)    running row max
//   fsS   : float [64]          @ 45568  (256)    per-chunk rescale factor
#define KOUT_SMEM 45824

__global__ __launch_bounds__(256, 4) void k_out(const int* __restrict__ A)
{
    extern __shared__ char smemraw[];
    uint32_t (*maskC)[8] = (uint32_t(*)[8])smemraw;
    float*  s2S    = (float*)(smemraw + 2048);
    float2* s2pair = (float2*)(smemraw + 6144);
    float*  whsP   = (float*)(smemraw + 10240);
    float*  s1s    = (float*)(smemraw + 45056);
    float*  msS    = (float*)(smemraw + 45312);
    float*  fsS    = (float*)(smemraw + 45568);

    int t = threadIdx.x;
    int lane = t & 31;
    int warp = t >> 5;
    int grp  = t >> 7;
    int lt   = t & 127;
    int wg   = warp & 3;
    int g = lane >> 2, tg = lane & 3;
    int m0 = wg * 16;

    int bid  = blockIdx.x;
    int half = bid & 1;
    int tile = bid >> 1;
    int b  = tile >> 5;
    int i0 = (tile & 31) << 6;
    int J0 = half << 10;
    const int* Ab = A + (size_t)b * CC * CC;

    if (t < 64) {
        s1s[t] = g_s1[b * CC + i0 + t];
        msS[t] = -3.0e38f;
    }
    for (int q = t; q < 1024; q += 256) s2S[q] = g_s2[b * CC + J0 + q];
    __syncthreads();
#pragma unroll
    for (int p = 0; p < 2; p++) {
        int idx = t + p * 256;
        int gj = idx >> 2, tgq = idx & 3;
        s2pair[idx] = make_float2(s2S[gj * 8 + tgq], s2S[gj * 8 + tgq + 4]);
    }

    float4 acc[8];
#pragma unroll
    for (int nf = 0; nf < 8; nf++) acc[nf] = make_float4(0.f, 0.f, 0.f, 0.f);
    float lA = 0.f, lB = 0.f;

    int gbase = (b * 32) + (J0 >> 6);
    int myrowA = m0 + g, myrowB = m0 + g + 8;

    for (int o = 0; o < 8; o++) {
        __syncthreads();                     // protect maskC/whsP/fsS reuse

        // -- stage Wh tile o (independent LDGs, issued early) --
        {
            const float4* src = (const float4*)(g_WhP + (size_t)(gbase + o * 2) * 4096);
#pragma unroll
            for (int p = 0; p < 8; p++) {
                int idx = t + p * 256;
                int gs = idx >> 10, rest = idx & 1023;
                int kt = rest >> 5, f4i = rest & 31;
                *(float4*)(whsP + gs * 4352 + kt * 136 + f4i * 4) = src[idx];
            }
        }

        // -- compress chunk o: 8 rows per warp, 128 j (1 int4/lane/row) --
#pragma unroll
        for (int rr = 0; rr < 8; rr++) {
            int rowl = warp * 8 + rr;
            int diagr = (i0 + rowl) - (J0 + o * 128);   // diag j rel. to chunk
            int4 av = __ldcs((const int4*)(Ab + (size_t)(i0 + rowl) * CC + J0 + o * 128) + lane);
            int jr = lane * 4;
            bool v0 = (av.x > 0) || (jr     == diagr);
            bool v1 = (av.y > 0) || (jr + 1 == diagr);
            bool v2 = (av.z > 0) || (jr + 2 == diagr);
            bool v3 = (av.w > 0) || (jr + 3 == diagr);
            uint32_t b0 = __ballot_sync(0xffffffffu, v0);
            uint32_t b1 = __ballot_sync(0xffffffffu, v1);
            uint32_t b2 = __ballot_sync(0xffffffffu, v2);
            uint32_t b3 = __ballot_sync(0xffffffffu, v3);
            float4 sv = *(const float4*)(s2S + o * 128 + jr);
            float m2 = -3.0e38f;
            m2 = fmaxf(m2, v0 ? sv.x : -3.0e38f);
            m2 = fmaxf(m2, v1 ? sv.y : -3.0e38f);
            m2 = fmaxf(m2, v2 ? sv.z : -3.0e38f);
            m2 = fmaxf(m2, v3 ? sv.w : -3.0e38f);
#pragma unroll
            for (int off = 16; off; off >>= 1)
                m2 = fmaxf(m2, __shfl_xor_sync(0xffffffffu, m2, off));
            if (lane == 0) {
                maskC[rowl][0] = b0;
                maskC[rowl][1] = b1;
                maskC[rowl][2] = b2;
                maskC[rowl][3] = b3;
                float xm = s1s[rowl] + m2;
                xm = fmaxf(xm, 0.2f * xm);              // chunk logit max
                float mo = msS[rowl];
                float mn = fmaxf(mo, xm);
                fsS[rowl] = ex2f(mo - mn);              // rescale factor (0 if first)
                msS[rowl] = mn;
            }
        }
        __syncthreads();

        // -- rescale accumulators by this chunk's factor --
        float fA = fsS[myrowA], fB = fsS[myrowB];
        float mAv = msS[myrowA], mBv = msS[myrowB];
        float s1A = s1s[myrowA], s1B = s1s[myrowB];
        float cA  = s1A - mAv,  c5A = 0.2f * s1A - mAv;
        float cB  = s1B - mBv,  c5B = 0.2f * s1B - mBv;
#pragma unroll
        for (int nf = 0; nf < 8; nf++) {
            acc[nf].x *= fA; acc[nf].y *= fA;
            acc[nf].z *= fB; acc[nf].w *= fB;
        }
        lA *= fA; lB *= fB;

        uint32_t mwA = maskC[myrowA][tg];
        uint32_t mwB = maskC[myrowB][tg];
        const float2* s2pg = s2pair + (o * 16 + grp * 8) * 4 + tg;
        const float*  wpg  = whsP + grp * 4352 + tg * 136;

#pragma unroll
        for (int kk = 0; kk < 8; kk++) {
            float2 sp = s2pg[kk * 4];
            int bit0 = grp * 16 + kk * 2, bit1 = bit0 + 1;

            float ya0 = fmaxf(sp.x + cA, fmaf(0.2f, sp.x, c5A));
            float ya1 = fmaxf(sp.y + cA, fmaf(0.2f, sp.y, c5A));
            float yb0 = fmaxf(sp.x + cB, fmaf(0.2f, sp.x, c5B));
            float yb1 = fmaxf(sp.y + cB, fmaf(0.2f, sp.y, c5B));

            ya0 = ((mwA >> bit0) & 1u) ? ya0 : -1000.f;
            ya1 = ((mwA >> bit1) & 1u) ? ya1 : -1000.f;
            yb0 = ((mwB >> bit0) & 1u) ? yb0 : -1000.f;
            yb1 = ((mwB >> bit1) & 1u) ? yb1 : -1000.f;

            float pa0 = f2tf32f(ex2f(ya0));
            float pa1 = f2tf32f(ex2f(ya1));
            float pb0 = f2tf32f(ex2f(yb0));
            float pb1 = f2tf32f(ex2f(yb1));
            lA += pa0 + pa1;
            lB += pb0 + pb1;

            uint32_t a0 = __float_as_uint(pa0);
            uint32_t a1 = __float_as_uint(pb0);
            uint32_t a2 = __float_as_uint(pa1);
            uint32_t a3 = __float_as_uint(pb1);

            const float* wk = wpg + kk * 4 * 136 + g * 2;
#pragma unroll
            for (int nf = 0; nf < 8; nf++) {
                float2 wp = *(const float2*)(wk + nf * 16);
                mma_tf32((float*)&acc[nf],
                         a0, a1, a2, a3,
                         __float_as_uint(wp.x), __float_as_uint(wp.y));
            }
        }
    }

    // ---- cross-group reduction (alias whsP) + scratch write ----
    __syncthreads();
    if (t < 64) g_partm[bid][t] = msS[t];
    float4* accS = (float4*)whsP;
    if (grp == 1) {
#pragma unroll
        for (int nf = 0; nf < 8; nf++) accS[lt * 9 + nf] = acc[nf];
        accS[lt * 9 + 8] = make_float4(lA, lB, 0.f, 0.f);
    }
    __syncthreads();
    if (grp == 0) {
#pragma unroll
        for (int nf = 0; nf < 8; nf++) {
            float4 o = accS[lt * 9 + nf];
            acc[nf].x += o.x; acc[nf].y += o.y; acc[nf].z += o.z; acc[nf].w += o.w;
        }
        float4 lo = accS[lt * 9 + 8];
        lA += lo.x; lB += lo.y;
        lA += __shfl_xor_sync(0xffffffffu, lA, 1);
        lA += __shfl_xor_sync(0xffffffffu, lA, 2);
        lB += __shfl_xor_sync(0xffffffffu, lB, 1);
        lB += __shfl_xor_sync(0xffffffffu, lB, 2);

        int row_lo = m0 + g, row_hi = row_lo + 8;
#pragma unroll
        for (int nf = 0; nf < 8; nf++) {
            int col = nf * 8 + 2 * tg;
            *(float2*)&g_part[bid][row_lo][col] = make_float2(acc[nf].x, acc[nf].y);
            *(float2*)&g_part[bid][row_hi][col] = make_float2(acc[nf].z, acc[nf].w);
        }
        if (tg == 0) {
            g_part[bid][row_lo][64] = lA;
            g_part[bid][row_hi][64] = lB;
        }
    }
}

// ---------------------------------------------------------------------------
// k_comb: weighted combine of halves (independent running maxes):
// out = relu((Σ acc_h w_h) / (Σ l_h w_h)),  w_h = exp2(m_h - max(m)).
// ---------------------------------------------------------------------------
__global__ __launch_bounds__(256) void k_comb(float* __restrict__ out)
{
    int tile = blockIdx.x;
    int t = threadIdx.x;
    int ri = t >> 2, cq = t & 3;
    int p0 = tile * 2, p1 = p0 + 1;

    float m0 = g_partm[p0][ri], m1 = g_partm[p1][ri];
    float M = fmaxf(m0, m1);
    float w0 = ex2f(m0 - M), w1 = ex2f(m1 - M);
    float l = g_part[p0][ri][64] * w0 + g_part[p1][ri][64] * w1;
    float inv = 1.f / l;

    size_t rowbase = ((size_t)tile * 64 + ri) * FF;
#pragma unroll
    for (int q = 0; q < 4; q++) {
        int col = cq * 16 + q * 4;
        float4 a0 = *(const float4*)&g_part[p0][ri][col];
        float4 a1 = *(const float4*)&g_part[p1][ri][col];
        float4 v;
        v.x = fmaxf((a0.x * w0 + a1.x * w1) * inv, 0.f);
        v.y = fmaxf((a0.y * w0 + a1.y * w1) * inv, 0.f);
        v.z = fmaxf((a0.z * w0 + a1.z * w1) * inv, 0.f);
        v.w = fmaxf((a0.w * w0 + a1.w * w1) * inv, 0.f);
        *(float4*)(out + rowbase + col) = v;
    }
}

// ---------------------------------------------------------------------------
extern "C" void kernel_launch(void* const* d_in, const int* in_sizes, int n_in,
                              void* d_out, int out_size)
{
    const float* H = (const float*)d_in[0];   // (8, 2048, 128) f32
    const int*   A = (const int*)d_in[1];     // (8, 2048, 2048) i32
    const float* W = (const float*)d_in[2];   // (128, 64) f32
    const float* a = (const float*)d_in[3];   // (128,) f32
    float* out = (float*)d_out;               // (8, 2048, 64) f32

    cudaFuncSetAttribute(k_out, cudaFuncAttributeMaxDynamicSharedMemorySize, KOUT_SMEM);

    k_wh<<<NROWS / 64, 256>>>(H, W, a);
    k_out<<<512, 256, KOUT_SMEM>>>(A);
    k_comb<<<256, 256>>>(out);
}

// round 12
// speedup vs baseline: 1.6456x; 1.1288x over previous
#include <cuda_runtime.h>
#include <cuda_bf16.h>
#include <cstdint>

#define BB 8
#define CC 2048
#define FIN 128
#define FF 64
#define NROWS (BB*CC)
#define LOG2E 1.4426950408889634f

// Scratch (__device__ globals: allocation-free rule)
// g_WhP: paired layout, per 64-row group (= global row>>6), 4096 floats:
//   offset = grp64*4096 + kt*128 + col*2 + h,  kt=(q>>3)*4+(q&3), h=(q>>2)&1.
__device__ float g_WhP[(size_t)NROWS * FF];
__device__ float g_s1[NROWS];                 // s1 * log2e
__device__ float g_s2[NROWS];                 // s2 * log2e
__device__ float g_part[512][64][72];         // per (tile,half): unnorm acc + l at col 64
__device__ float g_partm[512][64];            // per (tile,half): running row max (exp2 dom)

__device__ __forceinline__ float f2tf32f(float x) {
    uint32_t r;
    asm("cvt.rna.tf32.f32 %0, %1;" : "=r"(r) : "f"(x));
    return __uint_as_float(r);
}
__device__ __forceinline__ float ex2f(float x) {
    float r;
    asm("ex2.approx.f32 %0, %1;" : "=f"(r) : "f"(x));
    return r;
}
__device__ __forceinline__ void mma_tf32(float* c,
                                         uint32_t a0, uint32_t a1, uint32_t a2, uint32_t a3,
                                         uint32_t b0, uint32_t b1) {
    asm volatile(
        "mma.sync.aligned.m16n8k8.row.col.f32.tf32.tf32.f32 "
        "{%0,%1,%2,%3}, {%4,%5,%6,%7}, {%8,%9}, {%0,%1,%2,%3};"
        : "+f"(c[0]), "+f"(c[1]), "+f"(c[2]), "+f"(c[3])
        : "r"(a0), "r"(a1), "r"(a2), "r"(a3), "r"(b0), "r"(b1));
}
__device__ __forceinline__ int hperm(int r) { return r + ((r >> 3) << 2); }

// ---------------------------------------------------------------------------
// Kernel 1 (R8 verbatim): Wh = H @ W (64 rows/block, grid 256), + s1,s2.
// ---------------------------------------------------------------------------
__global__ __launch_bounds__(256) void k_wh(const float* __restrict__ H,
                                            const float* __restrict__ W,
                                            const float* __restrict__ a)
{
    __shared__ float HsT[32][92];
    __shared__ float Ws[32][68];

    int t  = threadIdx.x;
    int tx = t & 31;
    int ty = t >> 5;
    int r0 = blockIdx.x * 64;

    float acc[8][2] = {};

    for (int kc = 0; kc < 4; kc++) {
        __syncthreads();
#pragma unroll
        for (int p = 0; p < 2; p++) {
            int idx = t + p * 256;
            int r = idx >> 3, c4 = idx & 7;
            float4 v = *(const float4*)(H + (size_t)(r0 + r) * FIN + kc * 32 + c4 * 4);
            int pr = hperm(r);
            HsT[c4 * 4 + 0][pr] = v.x;
            HsT[c4 * 4 + 1][pr] = v.y;
            HsT[c4 * 4 + 2][pr] = v.z;
            HsT[c4 * 4 + 3][pr] = v.w;
        }
#pragma unroll
        for (int p = 0; p < 2; p++) {
            int idx = t + p * 256;
            int row = idx >> 4, c4 = idx & 15;
            *(float4*)&Ws[row][c4 * 4] = *(const float4*)(W + (size_t)(kc * 32 + row) * FF + c4 * 4);
        }
        __syncthreads();

#pragma unroll
        for (int k = 0; k < 32; k++) {
            float2 w = *(const float2*)&Ws[k][tx * 2];
            float4 h0 = *(const float4*)&HsT[k][ty * 12];
            float4 h1 = *(const float4*)&HsT[k][ty * 12 + 4];
            acc[0][0] = fmaf(h0.x, w.x, acc[0][0]); acc[0][1] = fmaf(h0.x, w.y, acc[0][1]);
            acc[1][0] = fmaf(h0.y, w.x, acc[1][0]); acc[1][1] = fmaf(h0.y, w.y, acc[1][1]);
            acc[2][0] = fmaf(h0.z, w.x, acc[2][0]); acc[2][1] = fmaf(h0.z, w.y, acc[2][1]);
            acc[3][0] = fmaf(h0.w, w.x, acc[3][0]); acc[3][1] = fmaf(h0.w, w.y, acc[3][1]);
            acc[4][0] = fmaf(h1.x, w.x, acc[4][0]); acc[4][1] = fmaf(h1.x, w.y, acc[4][1]);
            acc[5][0] = fmaf(h1.y, w.x, acc[5][0]); acc[5][1] = fmaf(h1.y, w.y, acc[5][1]);
            acc[6][0] = fmaf(h1.z, w.x, acc[6][0]); acc[6][1] = fmaf(h1.z, w.y, acc[6][1]);
            acc[7][0] = fmaf(h1.w, w.x, acc[7][0]); acc[7][1] = fmaf(h1.w, w.y, acc[7][1]);
        }
    }

    float a10 = a[tx * 2], a11 = a[tx * 2 + 1];
    float a20 = a[FF + tx * 2], a21 = a[FF + tx * 2 + 1];
#pragma unroll
    for (int rr = 0; rr < 8; rr++) {
        int r = r0 + ty * 8 + rr;
        float p1 = acc[rr][0] * a10 + acc[rr][1] * a11;
        float p2 = acc[rr][0] * a20 + acc[rr][1] * a21;
#pragma unroll
        for (int off = 16; off; off >>= 1) {
            p1 += __shfl_xor_sync(0xffffffffu, p1, off);
            p2 += __shfl_xor_sync(0xffffffffu, p2, off);
        }
        if (tx == 0) { g_s1[r] = p1 * LOG2E; g_s2[r] = p2 * LOG2E; }
    }

    float* dst = g_WhP + (size_t)blockIdx.x * 4096;
#pragma unroll
    for (int rr = 0; rr < 4; rr++) {
        int kt = ty * 4 + rr;
        float4 v;
        v.x = f2tf32f(acc[rr][0]);
        v.y = f2tf32f(acc[rr + 4][0]);
        v.z = f2tf32f(acc[rr][1]);
        v.w = f2tf32f(acc[rr + 4][1]);
        *(float4*)(dst + kt * 128 + tx * 4) = v;
    }
}

// ---------------------------------------------------------------------------
// k_out: SINGLE-PASS online-softmax @ Wh. Grid 512, 4 blocks/SM, one wave.
// Per 128-j chunk: cp.async-stage Wh (drains during compress), depth-2
// pipelined A loads -> ballot mask + chunk max, online rescale, exp+MMA.
// p fed to HMMA as raw fp32 (HW tf32-truncates); Wh pre-rounded RNA in k_wh.
// ---------------------------------------------------------------------------
// dynamic smem (bytes):
//   maskC : uint32[64][8]       @ 0      (2048)
//   s2S   : float [1024]        @ 2048   (4096)
//   s2pair: float2[512]         @ 6144   (4096)
//   whsP  : float [2][4352]     @ 10240  (34816)  (aliased as accS at end)
//   s1s   : float [64]          @ 45056  (256)
//   msS   : float [64]          @ 45312  (256)
//   fsS   : float [64]          @ 45568  (256)
#define KOUT_SMEM 45824

__global__ __launch_bounds__(256, 4) void k_out(const int* __restrict__ A)
{
    extern __shared__ char smemraw[];
    uint32_t (*maskC)[8] = (uint32_t(*)[8])smemraw;
    float*  s2S    = (float*)(smemraw + 2048);
    float2* s2pair = (float2*)(smemraw + 6144);
    float*  whsP   = (float*)(smemraw + 10240);
    float*  s1s    = (float*)(smemraw + 45056);
    float*  msS    = (float*)(smemraw + 45312);
    float*  fsS    = (float*)(smemraw + 45568);

    int t = threadIdx.x;
    int lane = t & 31;
    int warp = t >> 5;
    int grp  = t >> 7;
    int lt   = t & 127;
    int wg   = warp & 3;
    int g = lane >> 2, tg = lane & 3;
    int m0 = wg * 16;

    int bid  = blockIdx.x;
    int half = bid & 1;
    int tile = bid >> 1;
    int b  = tile >> 5;
    int i0 = (tile & 31) << 6;
    int J0 = half << 10;
    const int* Ab = A + (size_t)b * CC * CC;

    if (t < 64) {
        s1s[t] = g_s1[b * CC + i0 + t];
        msS[t] = -3.0e38f;
    }
    for (int q = t; q < 1024; q += 256) s2S[q] = g_s2[b * CC + J0 + q];
    __syncthreads();
#pragma unroll
    for (int p = 0; p < 2; p++) {
        int idx = t + p * 256;
        int gj = idx >> 2, tgq = idx & 3;
        s2pair[idx] = make_float2(s2S[gj * 8 + tgq], s2S[gj * 8 + tgq + 4]);
    }

    float4 acc[8];
#pragma unroll
    for (int nf = 0; nf < 8; nf++) acc[nf] = make_float4(0.f, 0.f, 0.f, 0.f);
    float lA = 0.f, lB = 0.f;

    int gbase = (b * 32) + (J0 >> 6);
    int myrowA = m0 + g, myrowB = m0 + g + 8;

    // precompute cp.async smem byte addresses' base
    uint32_t whs_sb = (uint32_t)__cvta_generic_to_shared(whsP);

    for (int o = 0; o < 8; o++) {
        __syncthreads();                     // protect maskC/whsP/fsS reuse

        // -- stage Wh tile o via cp.async (drains during compress) --
        {
            const float4* src = (const float4*)(g_WhP + (size_t)(gbase + o * 2) * 4096);
#pragma unroll
            for (int p = 0; p < 8; p++) {
                int idx = t + p * 256;
                int gs = idx >> 10, rest = idx & 1023;
                int kt = rest >> 5, f4i = rest & 31;
                uint32_t daddr = whs_sb + (uint32_t)(gs * 4352 + kt * 136 + f4i * 4) * 4u;
                asm volatile("cp.async.cg.shared.global [%0], [%1], 16;"
                             :: "r"(daddr), "l"(src + idx));
            }
            asm volatile("cp.async.commit_group;");
        }

        // -- compress chunk o: 8 rows/warp, depth-2 pipelined A loads --
        {
            const int4* abase = (const int4*)(Ab + (size_t)(i0 + warp * 8) * CC + J0 + o * 128) + lane;
            int4 av = __ldcs(abase);
#pragma unroll
            for (int rr = 0; rr < 8; rr++) {
                int4 nv = av;
                if (rr < 7) nv = __ldcs(abase + (rr + 1) * (CC / 4));
                int rowl = warp * 8 + rr;
                int diagr = (i0 + rowl) - (J0 + o * 128);
                int jr = lane * 4;
                bool v0 = (av.x > 0) || (jr     == diagr);
                bool v1 = (av.y > 0) || (jr + 1 == diagr);
                bool v2 = (av.z > 0) || (jr + 2 == diagr);
                bool v3 = (av.w > 0) || (jr + 3 == diagr);
                uint32_t b0 = __ballot_sync(0xffffffffu, v0);
                uint32_t b1 = __ballot_sync(0xffffffffu, v1);
                uint32_t b2 = __ballot_sync(0xffffffffu, v2);
                uint32_t b3 = __ballot_sync(0xffffffffu, v3);
                float4 sv = *(const float4*)(s2S + o * 128 + jr);
                float m2 = -3.0e38f;
                m2 = fmaxf(m2, v0 ? sv.x : -3.0e38f);
                m2 = fmaxf(m2, v1 ? sv.y : -3.0e38f);
                m2 = fmaxf(m2, v2 ? sv.z : -3.0e38f);
                m2 = fmaxf(m2, v3 ? sv.w : -3.0e38f);
#pragma unroll
                for (int off = 16; off; off >>= 1)
                    m2 = fmaxf(m2, __shfl_xor_sync(0xffffffffu, m2, off));
                if (lane == 0) {
                    maskC[rowl][0] = b0;
                    maskC[rowl][1] = b1;
                    maskC[rowl][2] = b2;
                    maskC[rowl][3] = b3;
                    float xm = s1s[rowl] + m2;
                    xm = fmaxf(xm, 0.2f * xm);          // chunk logit max
                    float mo = msS[rowl];
                    float mn = fmaxf(mo, xm);
                    fsS[rowl] = ex2f(mo - mn);          // rescale (0 if first)
                    msS[rowl] = mn;
                }
                av = nv;
            }
        }
        asm volatile("cp.async.wait_group 0;" ::: "memory");
        __syncthreads();

        // -- rescale accumulators by this chunk's factor --
        float fA = fsS[myrowA], fB = fsS[myrowB];
        float mAv = msS[myrowA], mBv = msS[myrowB];
        float s1A = s1s[myrowA], s1B = s1s[myrowB];
        float cA  = s1A - mAv,  c5A = 0.2f * s1A - mAv;
        float cB  = s1B - mBv,  c5B = 0.2f * s1B - mBv;
#pragma unroll
        for (int nf = 0; nf < 8; nf++) {
            acc[nf].x *= fA; acc[nf].y *= fA;
            acc[nf].z *= fB; acc[nf].w *= fB;
        }
        lA *= fA; lB *= fB;

        uint32_t mwA = maskC[myrowA][tg];
        uint32_t mwB = maskC[myrowB][tg];
        const float2* s2pg = s2pair + (o * 16 + grp * 8) * 4 + tg;
        const float*  wpg  = whsP + grp * 4352 + tg * 136;

#pragma unroll
        for (int kk = 0; kk < 8; kk++) {
            float2 sp = s2pg[kk * 4];
            int bit0 = grp * 16 + kk * 2, bit1 = bit0 + 1;

            float ya0 = fmaxf(sp.x + cA, fmaf(0.2f, sp.x, c5A));
            float ya1 = fmaxf(sp.y + cA, fmaf(0.2f, sp.y, c5A));
            float yb0 = fmaxf(sp.x + cB, fmaf(0.2f, sp.x, c5B));
            float yb1 = fmaxf(sp.y + cB, fmaf(0.2f, sp.y, c5B));

            ya0 = ((mwA >> bit0) & 1u) ? ya0 : -1000.f;
            ya1 = ((mwA >> bit1) & 1u) ? ya1 : -1000.f;
            yb0 = ((mwB >> bit0) & 1u) ? yb0 : -1000.f;
            yb1 = ((mwB >> bit1) & 1u) ? yb1 : -1000.f;

            // raw fp32 p; HMMA.TF32 truncates operands to tf32 in HW
            float pa0 = ex2f(ya0);
            float pa1 = ex2f(ya1);
            float pb0 = ex2f(yb0);
            float pb1 = ex2f(yb1);
            lA += pa0 + pa1;
            lB += pb0 + pb1;

            uint32_t a0 = __float_as_uint(pa0);
            uint32_t a1 = __float_as_uint(pb0);
            uint32_t a2 = __float_as_uint(pa1);
            uint32_t a3 = __float_as_uint(pb1);

            const float* wk = wpg + kk * 4 * 136 + g * 2;
#pragma unroll
            for (int nf = 0; nf < 8; nf++) {
                float2 wp = *(const float2*)(wk + nf * 16);
                mma_tf32((float*)&acc[nf],
                         a0, a1, a2, a3,
                         __float_as_uint(wp.x), __float_as_uint(wp.y));
            }
        }
    }

    // ---- cross-group reduction (alias whsP) + scratch write ----
    __syncthreads();
    if (t < 64) g_partm[bid][t] = msS[t];
    float4* accS = (float4*)whsP;
    if (grp == 1) {
#pragma unroll
        for (int nf = 0; nf < 8; nf++) accS[lt * 9 + nf] = acc[nf];
        accS[lt * 9 + 8] = make_float4(lA, lB, 0.f, 0.f);
    }
    __syncthreads();
    if (grp == 0) {
#pragma unroll
        for (int nf = 0; nf < 8; nf++) {
            float4 o = accS[lt * 9 + nf];
            acc[nf].x += o.x; acc[nf].y += o.y; acc[nf].z += o.z; acc[nf].w += o.w;
        }
        float4 lo = accS[lt * 9 + 8];
        lA += lo.x; lB += lo.y;
        lA += __shfl_xor_sync(0xffffffffu, lA, 1);
        lA += __shfl_xor_sync(0xffffffffu, lA, 2);
        lB += __shfl_xor_sync(0xffffffffu, lB, 1);
        lB += __shfl_xor_sync(0xffffffffu, lB, 2);

        int row_lo = m0 + g, row_hi = row_lo + 8;
#pragma unroll
        for (int nf = 0; nf < 8; nf++) {
            int col = nf * 8 + 2 * tg;
            *(float2*)&g_part[bid][row_lo][col] = make_float2(acc[nf].x, acc[nf].y);
            *(float2*)&g_part[bid][row_hi][col] = make_float2(acc[nf].z, acc[nf].w);
        }
        if (tg == 0) {
            g_part[bid][row_lo][64] = lA;
            g_part[bid][row_hi][64] = lB;
        }
    }
}

// ---------------------------------------------------------------------------
// k_comb: weighted combine of halves: out = relu((Σ acc_h w_h)/(Σ l_h w_h)),
// w_h = exp2(m_h - max(m)).
// ---------------------------------------------------------------------------
__global__ __launch_bounds__(256) void k_comb(float* __restrict__ out)
{
    int tile = blockIdx.x;
    int t = threadIdx.x;
    int ri = t >> 2, cq = t & 3;
    int p0 = tile * 2, p1 = p0 + 1;

    float m0 = g_partm[p0][ri], m1 = g_partm[p1][ri];
    float M = fmaxf(m0, m1);
    float w0 = ex2f(m0 - M), w1 = ex2f(m1 - M);
    float l = g_part[p0][ri][64] * w0 + g_part[p1][ri][64] * w1;
    float inv = 1.f / l;

    size_t rowbase = ((size_t)tile * 64 + ri) * FF;
#pragma unroll
    for (int q = 0; q < 4; q++) {
        int col = cq * 16 + q * 4;
        float4 a0 = *(const float4*)&g_part[p0][ri][col];
        float4 a1 = *(const float4*)&g_part[p1][ri][col];
        float4 v;
        v.x = fmaxf((a0.x * w0 + a1.x * w1) * inv, 0.f);
        v.y = fmaxf((a0.y * w0 + a1.y * w1) * inv, 0.f);
        v.z = fmaxf((a0.z * w0 + a1.z * w1) * inv, 0.f);
        v.w = fmaxf((a0.w * w0 + a1.w * w1) * inv, 0.f);
        *(float4*)(out + rowbase + col) = v;
    }
}

// ---------------------------------------------------------------------------
extern "C" void kernel_launch(void* const* d_in, const int* in_sizes, int n_in,
                              void* d_out, int out_size)
{
    const float* H = (const float*)d_in[0];   // (8, 2048, 128) f32
    const int*   A = (const int*)d_in[1];     // (8, 2048, 2048) i32
    const float* W = (const float*)d_in[2];   // (128, 64) f32
    const float* a = (const float*)d_in[3];   // (128,) f32
    float* out = (float*)d_out;               // (8, 2048, 64) f32

    cudaFuncSetAttribute(k_out, cudaFuncAttributeMaxDynamicSharedMemorySize, KOUT_SMEM);

    k_wh<<<NROWS / 64, 256>>>(H, W, a);
    k_out<<<512, 256, KOUT_SMEM>>>(A);
    k_comb<<<256, 256>>>(out);
}